// round 3
// baseline (speedup 1.0000x reference)
#include <cuda_runtime.h>
#include <math.h>

// NarrowParabolicEq: 1-D complex parabolic equation, fixed-step Dopri5.
// N=500 points, (n_save-1) intervals x 10 RK steps x 6 stages, sequential.
// Single CTA, 512 threads (1 point/thread), ping-pong shared buffers,
// one __syncthreads() per stage, volatile shared traffic (ordering-safe).
//
// OUTPUT LAYOUT: PLANAR complex — real plane [n_save*500] followed by
// imag plane [n_save*500] (harness flattens complex64 via real/imag stack).

#define NPTS 500
#define NTH  512
#define BUFN (NTH + 2)
#define N_INNER 10

__global__ __launch_bounds__(NTH, 1)
void pe_kernel(const float* __restrict__ params, float* __restrict__ out, int n_save)
{
    __shared__ float Ar_s[BUFN], Ai_s[BUFN], Br_s[BUFN], Bi_s[BUFN];
    volatile float* ar = Ar_s;  volatile float* ai = Ai_s;
    volatile float* br = Br_s;  volatile float* bi = Bi_s;

    const int i = threadIdx.x;
    const int half = n_save * NPTS;     // start of imag plane

    // ---------------- init (fp64, once) ----------------
    const double PI  = 3.14159265358979323846;
    const double K0d = 2.0 * PI * 50.0 / 1500.0;
    const double refc = (double)params[0];
    const double refd = (double)params[1];

    float yr = 0.0f, yi = 0.0f, CLI = 0.0f, CH = 0.0f;

    if (i < NPTS) {
        double z = 2000.0 * (double)i / 499.0;
        double ww  = sqrt(2.0 * log(2.0)) / (K0d * sin(PI / 180.0 * 1.5));
        double amp = 1.0 / (sqrt(PI) * ww);
        double a   = (z - 100.0) / ww;
        yr = (float)(amp * exp(-a * a));
        double zz  = 2.0 * (z - refd) / refd;
        double c   = refc * (1.0 + 0.00737 * (zz - 1.0 + exp(-zz)));
        double het = (1500.0 / c) * (1500.0 / c) - 1.0;
        if (i > 0 && i < NPTS - 1) {
            double dx = 2000.0 / 499.0;
            CH  = (float)(K0d * het);
            CLI = (float)((1.0 / (dx * dx)) / (2.0 * K0d));
        }
        out[i]        = yr;     // row 0, real plane
        out[half + i] = yi;     // row 0, imag plane
    }
    ar[i + 1] = yr;  ai[i + 1] = yi;
    br[i + 1] = 0.f; bi[i + 1] = 0.f;
    if (i == 0) {
        ar[0] = 0.f; ai[0] = 0.f; br[0] = 0.f; bi[0] = 0.f;
        ar[BUFN-1] = 0.f; ai[BUFN-1] = 0.f; br[BUFN-1] = 0.f; bi[BUFN-1] = 0.f;
    }
    __syncthreads();

    // ---------------- Dopri5 coefficients x DT (=0.1) ----------------
    const float HA21 = (float)(0.1 * (1.0/5.0));
    const float HA31 = (float)(0.1 * (3.0/40.0)),       HA32 = (float)(0.1 * (9.0/40.0));
    const float HA41 = (float)(0.1 * (44.0/45.0)),      HA42 = (float)(0.1 * (-56.0/15.0));
    const float HA43 = (float)(0.1 * (32.0/9.0));
    const float HA51 = (float)(0.1 * (19372.0/6561.0)), HA52 = (float)(0.1 * (-25360.0/2187.0));
    const float HA53 = (float)(0.1 * (64448.0/6561.0)), HA54 = (float)(0.1 * (-212.0/729.0));
    const float HA61 = (float)(0.1 * (9017.0/3168.0)),  HA62 = (float)(0.1 * (-355.0/33.0));
    const float HA63 = (float)(0.1 * (46732.0/5247.0)), HA64 = (float)(0.1 * (49.0/176.0));
    const float HA65 = (float)(0.1 * (-5103.0/18656.0));
    const float HB1  = (float)(0.1 * (35.0/384.0)),     HB3  = (float)(0.1 * (500.0/1113.0));
    const float HB4  = (float)(0.1 * (125.0/192.0)),    HB5  = (float)(0.1 * (-2187.0/6784.0));
    const float HB6  = (float)(0.1 * (11.0/84.0));

#define RHSK(RR, II, sr, si, kr, ki)                         \
    {                                                        \
        float _lr = RR[i] + RR[i+2] - 2.0f * (sr);           \
        float _li = II[i] + II[i+2] - 2.0f * (si);           \
        kr = -CLI * _li - CH * (si);                         \
        ki =  CLI * _lr + CH * (sr);                         \
    }

    const int nitv = n_save - 1;

    for (int itv = 0; itv < nitv; ++itv) {
        #pragma unroll 1
        for (int st = 0; st < N_INNER; ++st) {
            float k1r,k1i,k2r,k2i,k3r,k3i,k4r,k4i,k5r,k5i,k6r,k6i,tr,ti;

            RHSK(ar, ai, yr, yi, k1r, k1i);
            tr = yr + HA21*k1r;
            ti = yi + HA21*k1i;
            br[i+1] = tr; bi[i+1] = ti; __syncthreads();

            RHSK(br, bi, tr, ti, k2r, k2i);
            tr = yr + HA31*k1r + HA32*k2r;
            ti = yi + HA31*k1i + HA32*k2i;
            ar[i+1] = tr; ai[i+1] = ti; __syncthreads();

            RHSK(ar, ai, tr, ti, k3r, k3i);
            tr = yr + HA41*k1r + HA42*k2r + HA43*k3r;
            ti = yi + HA41*k1i + HA42*k2i + HA43*k3i;
            br[i+1] = tr; bi[i+1] = ti; __syncthreads();

            RHSK(br, bi, tr, ti, k4r, k4i);
            tr = yr + HA51*k1r + HA52*k2r + HA53*k3r + HA54*k4r;
            ti = yi + HA51*k1i + HA52*k2i + HA53*k3i + HA54*k4i;
            ar[i+1] = tr; ai[i+1] = ti; __syncthreads();

            RHSK(ar, ai, tr, ti, k5r, k5i);
            tr = yr + HA61*k1r + HA62*k2r + HA63*k3r + HA64*k4r + HA65*k5r;
            ti = yi + HA61*k1i + HA62*k2i + HA63*k3i + HA64*k4i + HA65*k5i;
            br[i+1] = tr; bi[i+1] = ti; __syncthreads();

            RHSK(br, bi, tr, ti, k6r, k6i);
            yr = yr + HB1*k1r + HB3*k3r + HB4*k4r + HB5*k5r + HB6*k6r;
            yi = yi + HB1*k1i + HB3*k3i + HB4*k4i + HB5*k5i + HB6*k6i;
            ar[i+1] = yr; ai[i+1] = yi; __syncthreads();
        }
        if (i < NPTS) {
            int row = (itv + 1) * NPTS + i;
            out[row]        = yr;   // real plane
            out[half + row] = yi;   // imag plane
        }
    }
#undef RHSK
}

extern "C" void kernel_launch(void* const* d_in, const int* in_sizes, int n_in,
                              void* d_out, int out_size)
{
    // Autodetect: params is the length-2 input, ts is the other.
    int p_idx = 1, t_idx = 0;
    if (n_in >= 2 && in_sizes[0] == 2 && in_sizes[1] != 2) { p_idx = 0; t_idx = 1; }
    const float* params = (const float*)d_in[p_idx];
    const int n_save = in_sizes[t_idx];
    pe_kernel<<<1, NTH>>>(params, (float*)d_out, n_save);
}

// round 4
// speedup vs baseline: 1.5833x; 1.5833x over previous
#include <cuda_runtime.h>
#include <math.h>

// NarrowParabolicEq — Horner form of the Dopri5 step.
// Linear RHS => one RK step is y' = R(hM) y with R(z) = sum c_k z^k,
// c = [1, 1, 1/2, 1/6, 1/24, 1/120, 1/600]. Evaluated by 6 tridiagonal
// applications per step, FUSED 2-per-barrier (5-pt redundant stencil):
// 3 barriers/step, 6000 barriers total (was 12000 stages).
// 256 threads, 2 points/thread, float4 shared traffic, planar output.

#define NPTS 500
#define NTH  256
#define SLOTS 516        // 2 pad + 512 + 2 pad ; logical point p -> slot p+2
#define N_INNER 10

__device__ __forceinline__ void coeffs_at(int q, double K0d, double refc, double refd,
                                          float* hcli, float* hch2)
{
    // z-operator coefficients at logical point q, premultiplied by h=DT=0.1:
    //  (zM t)_q.re = -hcli*(ti_{q-1}+ti_{q+1}) - hch2*ti_q   (and +.. for im)
    // hch2 folds the -2*CLI of the Laplacian center into the het term.
    if (q >= 1 && q <= NPTS - 2) {
        double dx = 2000.0 / 499.0;
        double cli = (1.0 / (dx * dx)) / (2.0 * K0d);
        double z  = 2000.0 * (double)q / 499.0;
        double zz = 2.0 * (z - refd) / refd;
        double c  = refc * (1.0 + 0.00737 * (zz - 1.0 + exp(-zz)));
        double het = (1500.0 / c) * (1500.0 / c) - 1.0;
        double ch = K0d * het;
        *hcli = (float)(0.1 * cli);
        *hch2 = (float)(0.1 * (ch - 2.0 * cli));
    } else {
        *hcli = 0.0f; *hch2 = 0.0f;
    }
}

__global__ __launch_bounds__(NTH, 1)
void pe_kernel(const float* __restrict__ params, float* __restrict__ out, int n_save)
{
    __shared__ __align__(16) float2 BUF0[SLOTS];
    __shared__ __align__(16) float2 BUF1[SLOTS];
    __shared__ __align__(16) float2 BUF2[SLOTS];
    __shared__ __align__(16) float2 BUF3[SLOTS];

    const int t  = threadIdx.x;
    const int p0 = 2 * t;          // owns logical points p0, p0+1
    const int sl = 2 * t;          // slot index of point p0-2
    const int half = n_save * NPTS;

    const double PI  = 3.14159265358979323846;
    const double K0d = 2.0 * PI * 50.0 / 1500.0;
    const double refc = (double)params[0];
    const double refd = (double)params[1];

    // ---- initial field (fp64 once) ----
    float y0r = 0.f, y0i = 0.f, y1r = 0.f, y1i = 0.f;
    {
        double ww  = sqrt(2.0 * log(2.0)) / (K0d * sin(PI / 180.0 * 1.5));
        double amp = 1.0 / (sqrt(PI) * ww);
        if (p0 < NPTS) {
            double z = 2000.0 * (double)p0 / 499.0;
            double a = (z - 100.0) / ww;
            y0r = (float)(amp * exp(-a * a));
            z = 2000.0 * (double)(p0 + 1) / 499.0;
            a = (z - 100.0) / ww;
            y1r = (float)(amp * exp(-a * a));
            out[p0] = y0r; out[p0 + 1] = y1r;            // row 0 real plane
            out[half + p0] = 0.f; out[half + p0 + 1] = 0.f; // row 0 imag plane
        }
    }

    // ---- per-thread operator coefficients at p0-1, p0, p1, p1+1 ----
    float clim, cli0, cli1, clip, chm, ch0, ch1, chp;
    coeffs_at(p0 - 1, K0d, refc, refd, &clim, &chm);
    coeffs_at(p0,     K0d, refc, refd, &cli0, &ch0);
    coeffs_at(p0 + 1, K0d, refc, refd, &cli1, &ch1);
    coeffs_at(p0 + 2, K0d, refc, refd, &clip, &chp);
    // c6-scaled copies for the first Horner application of each step
    const float C6 = (float)(1.0 / 600.0);
    const float sclim = C6 * clim, scli0 = C6 * cli0, scli1 = C6 * cli1, sclip = C6 * clip;
    const float schm  = C6 * chm,  sch0  = C6 * ch0,  sch1  = C6 * ch1,  schp  = C6 * chp;
    const float C5 = (float)(1.0 / 120.0);
    const float C4 = (float)(1.0 / 24.0);
    const float C3 = (float)(1.0 / 6.0);
    const float C2 = 0.5f;

    // ---- shared init: state into BUF0, pads of all buffers zeroed ----
    BUF0[sl + 2] = make_float2(y0r, y0i);
    BUF0[sl + 3] = make_float2(y1r, y1i);
    BUF1[sl + 2] = make_float2(0.f, 0.f); BUF1[sl + 3] = make_float2(0.f, 0.f);
    BUF2[sl + 2] = make_float2(0.f, 0.f); BUF2[sl + 3] = make_float2(0.f, 0.f);
    BUF3[sl + 2] = make_float2(0.f, 0.f); BUF3[sl + 3] = make_float2(0.f, 0.f);
    if (t < 2) {
        BUF0[t] = make_float2(0.f, 0.f); BUF0[514 + t] = make_float2(0.f, 0.f);
        BUF1[t] = make_float2(0.f, 0.f); BUF1[514 + t] = make_float2(0.f, 0.f);
        BUF2[t] = make_float2(0.f, 0.f); BUF2[514 + t] = make_float2(0.f, 0.f);
        BUF3[t] = make_float2(0.f, 0.f); BUF3[514 + t] = make_float2(0.f, 0.f);
    }
    __syncthreads();

    float t0r, t0i, t1r, t1i;          // Horner intermediate at own points
    float yLr = 0.f, yLi = 0.f, yRr = 0.f, yRi = 0.f; // y at p0-1, p1+1 (per step)

    // One fused pair: u = firstApp(SRC) with coeffs (CLm..), add CA*y;
    //                 t' = z u + CB*y (unscaled own coeffs). Stores t' -> DST.
    // GRABY=1 (first pair of a step): capture y halo from the loaded values.
#define ZPAIR(SRC, DST, CLm, CL0, CL1, CLp, CHm_, CH0_, CH1_, CHp_, CA, CB, GRABY)  \
    {                                                                                \
        float4 Lv = *reinterpret_cast<const float4*>(&(SRC)[sl]);                    \
        float4 Rv = *reinterpret_cast<const float4*>(&(SRC)[sl + 4]);                \
        float tm2r = Lv.x, tm2i = Lv.y, tm1r = Lv.z, tm1i = Lv.w;                    \
        float tp1r = Rv.x, tp1i = Rv.y, tp2r = Rv.z, tp2i = Rv.w;                    \
        if (GRABY) { yLr = tm1r; yLi = tm1i; yRr = tp1r; yRi = tp1i; }               \
        float sI, sR;                                                                \
        sI = tm2i + t0i; sR = tm2r + t0r;                                            \
        float umr = -(CLm) * sI - (CHm_) * tm1i + (CA) * yLr;                        \
        float umi =  (CLm) * sR + (CHm_) * tm1r + (CA) * yLi;                        \
        sI = tm1i + t1i; sR = tm1r + t1r;                                            \
        float u0r = -(CL0) * sI - (CH0_) * t0i + (CA) * y0r;                         \
        float u0i =  (CL0) * sR + (CH0_) * t0r + (CA) * y0i;                         \
        sI = t0i + tp1i; sR = t0r + tp1r;                                            \
        float u1r = -(CL1) * sI - (CH1_) * t1i + (CA) * y1r;                         \
        float u1i =  (CL1) * sR + (CH1_) * t1r + (CA) * y1i;                         \
        sI = t1i + tp2i; sR = t1r + tp2r;                                            \
        float upr = -(CLp) * sI - (CHp_) * tp1i + (CA) * yRr;                        \
        float upi =  (CLp) * sR + (CHp_) * tp1r + (CA) * yRi;                        \
        sI = umi + u1i; sR = umr + u1r;                                              \
        float n0r = -cli0 * sI - ch0 * u0i + (CB) * y0r;                             \
        float n0i =  cli0 * sR + ch0 * u0r + (CB) * y0i;                             \
        sI = u0i + upi; sR = u0r + upr;                                              \
        float n1r = -cli1 * sI - ch1 * u1i + (CB) * y1r;                             \
        float n1i =  cli1 * sR + ch1 * u1r + (CB) * y1i;                             \
        t0r = n0r; t0i = n0i; t1r = n1r; t1i = n1i;                                  \
        float4 stv; stv.x = t0r; stv.y = t0i; stv.z = t1r; stv.w = t1i;              \
        *reinterpret_cast<float4*>(&(DST)[sl + 2]) = stv;                            \
        __syncthreads();                                                             \
    }

    float2* Ycur = BUF0;
    float2* Yalt = BUF3;
    const int nitv = n_save - 1;

    for (int itv = 0; itv < nitv; ++itv) {
        #pragma unroll 1
        for (int st = 0; st < N_INNER; ++st) {
            t0r = y0r; t0i = y0i; t1r = y1r; t1i = y1i;
            // apps 1-2:  u = c6*(zY) + c5*Y ;  t = z u + c4*Y
            ZPAIR(Ycur, BUF1, sclim, scli0, scli1, sclip, schm, sch0, sch1, schp, C5, C4, 1)
            // apps 3-4:  u = z t + c3*Y ;      t = z u + c2*Y
            ZPAIR(BUF1, BUF2, clim, cli0, cli1, clip, chm, ch0, ch1, chp, C3, C2, 0)
            // apps 5-6:  u = z t + 1*Y ;       y' = z u + 1*Y
            ZPAIR(BUF2, Yalt, clim, cli0, cli1, clip, chm, ch0, ch1, chp, 1.0f, 1.0f, 0)
            y0r = t0r; y0i = t0i; y1r = t1r; y1i = t1i;
            float2* tmp = Ycur; Ycur = Yalt; Yalt = tmp;
        }
        if (p0 < NPTS) {
            int row = (itv + 1) * NPTS + p0;
            out[row]            = y0r;  out[row + 1]        = y1r;
            out[half + row]     = y0i;  out[half + row + 1] = y1i;
        }
    }
#undef ZPAIR
}

extern "C" void kernel_launch(void* const* d_in, const int* in_sizes, int n_in,
                              void* d_out, int out_size)
{
    int p_idx = 1, t_idx = 0;
    if (n_in >= 2 && in_sizes[0] == 2 && in_sizes[1] != 2) { p_idx = 0; t_idx = 1; }
    const float* params = (const float*)d_in[p_idx];
    const int n_save = in_sizes[t_idx];
    pe_kernel<<<1, NTH>>>(params, (float*)d_out, n_save);
}

// round 5
// speedup vs baseline: 1.7821x; 1.1256x over previous
#include <cuda_runtime.h>
#include <math.h>

// NarrowParabolicEq — Dopri5 step as Horner polynomial in the REAL operator.
// z = i*zeta, zeta = h*(CLI*T + CH2*I) has real per-point coefficients, so
// R(z)y = sum c_k i^k zeta^k y. Horner in zeta: every application is
// component-wise on (re,im) -> packed f32x2 ops. d_k*y addends use y or ys=i*y.
// 6 applications/step fused 2-per-barrier: 3 barriers/step, 6000 total.
// 256 threads, 2 points/thread, float4 shared traffic, planar output.

#define NPTS 500
#define NTH  256
#define SLOTS 516        // 2 pad + 512 + 2 pad ; logical point p -> slot p+2
#define N_INNER 10

typedef unsigned long long u64;
union F2U { float2 f; u64 u; };

__device__ __forceinline__ u64 pk2(float lo, float hi) { F2U x; x.f.x = lo; x.f.y = hi; return x.u; }
__device__ __forceinline__ u64 mulI(u64 v) { F2U a; a.u = v; F2U r; r.f.x = -a.f.y; r.f.y = a.f.x; return r.u; }
__device__ __forceinline__ float lo2(u64 v) { F2U a; a.u = v; return a.f.x; }
__device__ __forceinline__ float hi2(u64 v) { F2U a; a.u = v; return a.f.y; }

__device__ __forceinline__ u64 fma2(u64 a, u64 b, u64 c)
{ u64 d; asm("fma.rn.f32x2 %0,%1,%2,%3;" : "=l"(d) : "l"(a), "l"(b), "l"(c)); return d; }
__device__ __forceinline__ u64 add2(u64 a, u64 b)
{ u64 d; asm("add.rn.f32x2 %0,%1,%2;" : "=l"(d) : "l"(a), "l"(b)); return d; }
__device__ __forceinline__ u64 mul2(u64 a, u64 b)
{ u64 d; asm("mul.rn.f32x2 %0,%1,%2;" : "=l"(d) : "l"(a), "l"(b)); return d; }

__device__ __forceinline__ void coeffs_at(int q, double K0d, double refc, double refd,
                                          float* hcli, float* hch2)
{
    if (q >= 1 && q <= NPTS - 2) {
        double dx = 2000.0 / 499.0;
        double cli = (1.0 / (dx * dx)) / (2.0 * K0d);
        double z  = 2000.0 * (double)q / 499.0;
        double zz = 2.0 * (z - refd) / refd;
        double c  = refc * (1.0 + 0.00737 * (zz - 1.0 + exp(-zz)));
        double het = (1500.0 / c) * (1500.0 / c) - 1.0;
        double ch = K0d * het;
        *hcli = (float)(0.1 * cli);
        *hch2 = (float)(0.1 * (ch - 2.0 * cli));
    } else {
        *hcli = 0.0f; *hch2 = 0.0f;
    }
}

__global__ __launch_bounds__(NTH, 1)
void pe_kernel(const float* __restrict__ params, float* __restrict__ out, int n_save)
{
    __shared__ __align__(16) float2 BUF0[SLOTS];
    __shared__ __align__(16) float2 BUF1[SLOTS];
    __shared__ __align__(16) float2 BUF2[SLOTS];
    __shared__ __align__(16) float2 BUF3[SLOTS];

    const int t  = threadIdx.x;
    const int p0 = 2 * t;
    const int sl = 2 * t;            // slot of point p0-2
    const int half = n_save * NPTS;

    const double PI  = 3.14159265358979323846;
    const double K0d = 2.0 * PI * 50.0 / 1500.0;
    const double refc = (double)params[0];
    const double refd = (double)params[1];

    // ---- initial field ----
    float y0r = 0.f, y1r = 0.f;
    {
        double ww  = sqrt(2.0 * log(2.0)) / (K0d * sin(PI / 180.0 * 1.5));
        double amp = 1.0 / (sqrt(PI) * ww);
        if (p0 < NPTS) {
            double z = 2000.0 * (double)p0 / 499.0;
            double a = (z - 100.0) / ww;
            y0r = (float)(amp * exp(-a * a));
            z = 2000.0 * (double)(p0 + 1) / 499.0;
            a = (z - 100.0) / ww;
            y1r = (float)(amp * exp(-a * a));
            out[p0] = y0r; out[p0 + 1] = y1r;
            out[half + p0] = 0.f; out[half + p0 + 1] = 0.f;
        }
    }

    // ---- packed per-point operator coefficients ----
    float clim, cli0, cli1, clip, chm, ch0, ch1, chp;
    coeffs_at(p0 - 1, K0d, refc, refd, &clim, &chm);
    coeffs_at(p0,     K0d, refc, refd, &cli0, &ch0);
    coeffs_at(p0 + 1, K0d, refc, refd, &cli1, &ch1);
    coeffs_at(p0 + 2, K0d, refc, refd, &clip, &chp);

    const u64 LM = pk2(clim, clim), L0 = pk2(cli0, cli0), L1 = pk2(cli1, cli1), LP = pk2(clip, clip);
    const u64 HM = pk2(chm,  chm),  H0 = pk2(ch0,  ch0),  H1 = pk2(ch1,  ch1),  HP = pk2(chp,  chp);
    const float SC = (float)(-1.0 / 600.0);   // d6 = -c6
    const u64 sLM = pk2(SC * clim, SC * clim), sL0 = pk2(SC * cli0, SC * cli0);
    const u64 sL1 = pk2(SC * cli1, SC * cli1), sLP = pk2(SC * clip, SC * clip);
    const u64 sHM = pk2(SC * chm,  SC * chm),  sH0 = pk2(SC * ch0,  SC * ch0);
    const u64 sH1 = pk2(SC * ch1,  SC * ch1),  sHP = pk2(SC * chp,  SC * chp);
    const u64 C5P  = pk2((float)( 1.0/120.0), (float)( 1.0/120.0));
    const u64 C4P  = pk2((float)( 1.0/24.0),  (float)( 1.0/24.0));
    const u64 nC3P = pk2((float)(-1.0/6.0),   (float)(-1.0/6.0));
    const u64 nC2P = pk2(-0.5f, -0.5f);

    // ---- packed state ----
    u64 y0p = pk2(y0r, 0.f), y1p = pk2(y1r, 0.f);
    u64 ys0 = mulI(y0p),      ys1 = mulI(y1p);

    // ---- shared init ----
    BUF0[sl + 2] = make_float2(y0r, 0.f);
    BUF0[sl + 3] = make_float2(y1r, 0.f);
    BUF1[sl + 2] = make_float2(0.f, 0.f); BUF1[sl + 3] = make_float2(0.f, 0.f);
    BUF2[sl + 2] = make_float2(0.f, 0.f); BUF2[sl + 3] = make_float2(0.f, 0.f);
    BUF3[sl + 2] = make_float2(0.f, 0.f); BUF3[sl + 3] = make_float2(0.f, 0.f);
    if (t < 2) {
        BUF0[t] = make_float2(0.f, 0.f); BUF0[514 + t] = make_float2(0.f, 0.f);
        BUF1[t] = make_float2(0.f, 0.f); BUF1[514 + t] = make_float2(0.f, 0.f);
        BUF2[t] = make_float2(0.f, 0.f); BUF2[514 + t] = make_float2(0.f, 0.f);
        BUF3[t] = make_float2(0.f, 0.f); BUF3[514 + t] = make_float2(0.f, 0.f);
    }
    __syncthreads();

    float2* Ycur = BUF0;
    float2* Yalt = BUF3;
    const int nitv = n_save - 1;

    u64 t0, t1, yL, yR, ysL, ysR;

    // Load 4 halo values (points p0-2, p0-1, p1+1, p1+2) from SRC as packed u64.
#define LOADH(SRC, v0, v1, v2, v3)                                        \
        float4 Lv = *reinterpret_cast<const float4*>(&(SRC)[sl]);         \
        float4 Rv = *reinterpret_cast<const float4*>(&(SRC)[sl + 4]);     \
        u64 v0 = pk2(Lv.x, Lv.y), v1 = pk2(Lv.z, Lv.w);                   \
        u64 v2 = pk2(Rv.x, Rv.y), v3 = pk2(Rv.z, Rv.w);

#define STORE2(DST)                                                       \
        { float4 sv; sv.x = lo2(t0); sv.y = hi2(t0);                      \
          sv.z = lo2(t1); sv.w = hi2(t1);                                 \
          *reinterpret_cast<float4*>(&(DST)[sl + 2]) = sv; }              \
        __syncthreads();

    for (int itv = 0; itv < nitv; ++itv) {
        #pragma unroll 1
        for (int st = 0; st < N_INNER; ++st) {
            {   // pair 1: u = -c6*zeta(y) + c5*ys ;  t = zeta(u) + c4*y
                LOADH(Ycur, v0, v1, v2, v3)
                yL = v1; yR = v2; ysL = mulI(v1); ysR = mulI(v2);
                u64 um = fma2(sLM, add2(v0,  y0p), fma2(sHM, yL,  mul2(C5P, ysL)));
                u64 u0 = fma2(sL0, add2(yL,  y1p), fma2(sH0, y0p, mul2(C5P, ys0)));
                u64 u1 = fma2(sL1, add2(y0p, yR),  fma2(sH1, y1p, mul2(C5P, ys1)));
                u64 up = fma2(sLP, add2(y1p, v3),  fma2(sHP, yR,  mul2(C5P, ysR)));
                t0 = fma2(L0, add2(um, u1), fma2(H0, u0, mul2(C4P, y0p)));
                t1 = fma2(L1, add2(u0, up), fma2(H1, u1, mul2(C4P, y1p)));
                STORE2(BUF1)
            }
            {   // pair 2: u = zeta(t) - c3*ys ;  t = zeta(u) - c2*y
                LOADH(BUF1, v0, v1, v2, v3)
                u64 um = fma2(LM, add2(v0, t0), fma2(HM, v1, mul2(nC3P, ysL)));
                u64 u0 = fma2(L0, add2(v1, t1), fma2(H0, t0, mul2(nC3P, ys0)));
                u64 u1 = fma2(L1, add2(t0, v2), fma2(H1, t1, mul2(nC3P, ys1)));
                u64 up = fma2(LP, add2(t1, v3), fma2(HP, v2, mul2(nC3P, ysR)));
                u64 n0 = fma2(L0, add2(um, u1), fma2(H0, u0, mul2(nC2P, y0p)));
                u64 n1 = fma2(L1, add2(u0, up), fma2(H1, u1, mul2(nC2P, y1p)));
                t0 = n0; t1 = n1;
                STORE2(BUF2)
            }
            {   // pair 3: u = zeta(t) + ys ;  y' = zeta(u) + y
                LOADH(BUF2, v0, v1, v2, v3)
                u64 um = fma2(LM, add2(v0, t0), fma2(HM, v1, ysL));
                u64 u0 = fma2(L0, add2(v1, t1), fma2(H0, t0, ys0));
                u64 u1 = fma2(L1, add2(t0, v2), fma2(H1, t1, ys1));
                u64 up = fma2(LP, add2(t1, v3), fma2(HP, v2, ysR));
                y0p = fma2(L0, add2(um, u1), fma2(H0, u0, y0p));
                y1p = fma2(L1, add2(u0, up), fma2(H1, u1, y1p));
                t0 = y0p; t1 = y1p;
                STORE2(Yalt)
                ys0 = mulI(y0p); ys1 = mulI(y1p);
            }
            float2* tmp = Ycur; Ycur = Yalt; Yalt = tmp;
        }
        if (p0 < NPTS) {
            int row = (itv + 1) * NPTS + p0;
            out[row]            = lo2(y0p);  out[row + 1]        = lo2(y1p);
            out[half + row]     = hi2(y0p);  out[half + row + 1] = hi2(y1p);
        }
    }
#undef LOADH
#undef STORE2
}

extern "C" void kernel_launch(void* const* d_in, const int* in_sizes, int n_in,
                              void* d_out, int out_size)
{
    int p_idx = 1, t_idx = 0;
    if (n_in >= 2 && in_sizes[0] == 2 && in_sizes[1] != 2) { p_idx = 0; t_idx = 1; }
    const float* params = (const float*)d_in[p_idx];
    const int n_save = in_sizes[t_idx];
    pe_kernel<<<1, NTH>>>(params, (float*)d_out, n_save);
}